// round 14
// baseline (speedup 1.0000x reference)
#include <cuda_runtime.h>
#include <cuda_bf16.h>
#include <cstdint>

#define DEV_INLINE __device__ __forceinline__

constexpr int B_   = 4;
constexpr int K_   = 2048;
constexpr int P_   = 4096;
constexpr int NB   = 16;
constexpr int CIN  = 64;
constexpr int CMID = 32;
constexpr int FH   = 256;
constexpr int COUT = 128;
constexpr int GK   = B_ * K_;        // 8192 keys total
constexpr int EDIM = CMID * CIN;     // 2048

// Scratch (allocation-free rule: __device__ globals)
__device__ int            g_idx[GK * NB];
__device__ __nv_bfloat16  g_Ehi[(size_t)GK * EDIM];   // 32 MB
__device__ __nv_bfloat16  g_Elo[(size_t)GK * EDIM];   // 32 MB
__device__ __nv_bfloat16  g_Whi[(size_t)FH * EDIM];   // W0^T split, [256][2048]
__device__ __nv_bfloat16  g_Wlo[(size_t)FH * EDIM];
__device__ __nv_bfloat16  g_Hhi[(size_t)GK * FH];     // H split, [8192][256]
__device__ __nv_bfloat16  g_Hlo[(size_t)GK * FH];
__device__ __nv_bfloat16  g_W1hi[COUT * FH];          // W1^T split, [128][256]
__device__ __nv_bfloat16  g_W1lo[COUT * FH];

// ---------------------------------------------------------------------------
// PTX helpers (cp.async / ldmatrix / mma.sync — baseline sm_80+, plain sm_103 OK)
// ---------------------------------------------------------------------------
DEV_INLINE uint32_t smem_u32(const void* p) {
    return (uint32_t)__cvta_generic_to_shared(p);
}

DEV_INLINE void cp_async16(uint32_t dst, const void* src) {
    asm volatile("cp.async.cg.shared.global [%0], [%1], 16;"
                 :: "r"(dst), "l"(src) : "memory");
}
DEV_INLINE void cp_commit()  { asm volatile("cp.async.commit_group;" ::: "memory"); }
template <int N> DEV_INLINE void cp_wait() {
    asm volatile("cp.async.wait_group %0;" :: "n"(N) : "memory");
}

DEV_INLINE void ldm_x4(uint32_t* r, uint32_t addr) {
    asm volatile("ldmatrix.sync.aligned.m8n8.x4.shared.b16 {%0,%1,%2,%3}, [%4];"
                 : "=r"(r[0]), "=r"(r[1]), "=r"(r[2]), "=r"(r[3]) : "r"(addr));
}

DEV_INLINE void mma_bf16(float* d, const uint32_t* a, uint32_t b0, uint32_t b1) {
    asm volatile(
        "mma.sync.aligned.m16n8k16.row.col.f32.bf16.bf16.f32 "
        "{%0,%1,%2,%3}, {%4,%5,%6,%7}, {%8,%9}, {%0,%1,%2,%3};"
        : "+f"(d[0]), "+f"(d[1]), "+f"(d[2]), "+f"(d[3])
        : "r"(a[0]), "r"(a[1]), "r"(a[2]), "r"(a[3]), "r"(b0), "r"(b1));
}

// Split v0,v1 into bf16 hi (returned packed) and bf16 lo (out-param packed).
DEV_INLINE uint32_t pack_split(float v0, float v1, uint32_t& lo_out) {
    __nv_bfloat16 h0 = __float2bfloat16(v0);
    __nv_bfloat16 h1 = __float2bfloat16(v1);
    __nv_bfloat16 l0 = __float2bfloat16(v0 - __bfloat162float(h0));
    __nv_bfloat16 l1 = __float2bfloat16(v1 - __bfloat162float(h1));
    lo_out = ((uint32_t)__bfloat16_as_ushort(l1) << 16) | __bfloat16_as_ushort(l0);
    return ((uint32_t)__bfloat16_as_ushort(h1) << 16) | __bfloat16_as_ushort(h0);
}

// ---------------------------------------------------------------------------
// Kernel 1: fused prep + KNN (16 keys per block, 2 per warp).
// ---------------------------------------------------------------------------
__global__ void __launch_bounds__(256) knn_prep_kernel(
    const float* __restrict__ keys, const float* __restrict__ points,
    const float* __restrict__ W0, const float* __restrict__ W1)
{
    __shared__ float sp[P_ * 3];   // 48KB: points tile for knn / transpose tile for prep
    const int bx = blockIdx.x;

    if (bx < 512) {
        // --- W0 transpose-split ---
        float (*tile)[33] = (float(*)[33])sp;
        const int tx = threadIdx.x & 31, ty = threadIdx.x >> 5;
        const int k0 = (bx & 63) * 32, n0 = (bx >> 6) * 32;
#pragma unroll
        for (int i = 0; i < 4; ++i)
            tile[ty + i * 8][tx] = W0[(size_t)(k0 + ty + i * 8) * FH + n0 + tx];
        __syncthreads();
#pragma unroll
        for (int i = 0; i < 4; ++i) {
            const int nn = n0 + ty + i * 8, kk = k0 + tx;
            const float v = tile[tx][ty + i * 8];
            __nv_bfloat16 h = __float2bfloat16(v);
            g_Whi[(size_t)nn * EDIM + kk] = h;
            g_Wlo[(size_t)nn * EDIM + kk] = __float2bfloat16(v - __bfloat162float(h));
        }
        return;
    }
    if (bx < 640) {
        // --- W1 split ---
        const int idx = (bx - 512) * 256 + threadIdx.x;   // 0..32767
        const int nn = idx >> 8, kk = idx & 255;
        const float v = W1[kk * COUT + nn];
        __nv_bfloat16 h = __float2bfloat16(v);
        g_W1hi[nn * FH + kk] = h;
        g_W1lo[nn * FH + kk] = __float2bfloat16(v - __bfloat162float(h));
        return;
    }

    // --- KNN: 16 keys per block, warp handles 2 consecutive keys ---
    const int kb = bx - 640;
    const int warp = threadIdx.x >> 5;
    const int lane = threadIdx.x & 31;
    const int gbase = kb * 16 + warp * 2;
    const int b = gbase >> 11;            // whole block in one batch (16 | 2048)
    const unsigned FULL = 0xffffffffu;

    const float* pb = points + (size_t)b * P_ * 3;
    for (int i = threadIdx.x; i < P_ * 3; i += 256) sp[i] = pb[i];
    __syncthreads();

    for (int sub = 0; sub < 2; ++sub) {
        const int g = gbase + sub;
        const float kx = keys[g * 3 + 0];
        const float ky = keys[g * 3 + 1];
        const float kz = keys[g * 3 + 2];

        float ld = 3.4e38f;          // distributed list entry (lanes 0..15 valid)
        int   li = 0x7fffffff;
        float warpMax = 3.4e38f;     // current 16th smallest (uniform)

        for (int p = lane; p < P_; p += 32) {
            float dx = __fsub_rn(sp[p * 3 + 0], kx);
            float dy = __fsub_rn(sp[p * 3 + 1], ky);
            float dz = __fsub_rn(sp[p * 3 + 2], kz);
            float d  = __fadd_rn(__fadd_rn(__fmul_rn(dx, dx), __fmul_rn(dy, dy)),
                                 __fmul_rn(dz, dz));

            unsigned hit = __ballot_sync(FULL, d < warpMax);
            while (hit) {
                const int src = __ffs(hit) - 1;
                hit &= hit - 1;
                const float dc = __shfl_sync(FULL, d, src);
                const int   ic = __shfl_sync(FULL, p, src);
                if (dc < warpMax) {   // recheck: warpMax tightens within this loop
                    const unsigned bal =
                        __ballot_sync(FULL, (lane < NB) && (ld <= dc));
                    const int pos = __popc(bal);
                    const float pd = __shfl_up_sync(FULL, ld, 1);
                    const int   pi = __shfl_up_sync(FULL, li, 1);
                    if (lane >= pos && lane < NB) {
                        ld = (lane == pos) ? dc : pd;
                        li = (lane == pos) ? ic : pi;
                    }
                    warpMax = __shfl_sync(FULL, ld, NB - 1);
                }
            }
        }
        if (lane < NB) g_idx[g * NB + lane] = li;
    }
}

// ---------------------------------------------------------------------------
// Kernel 2: per-edge weight MLP + aggregation -> E (bf16 hi/lo, packed stores).
// (verified; unchanged)
// ---------------------------------------------------------------------------
__global__ void __launch_bounds__(128) edge_kernel(
    const float* __restrict__ keys, const float* __restrict__ points,
    const float* __restrict__ feats,
    const float* __restrict__ w0, const float* __restrict__ b0,
    const float* __restrict__ w1, const float* __restrict__ b1,
    const float* __restrict__ w2, const float* __restrict__ b2)
{
    __shared__ __align__(16) float sw0[3][32];
    __shared__ float sb0[32], sb1[32], sb2[32];
    __shared__ __align__(16) float sw1t[32][32];   // [out][in]
    __shared__ __align__(16) float sw2t[32][32];
    __shared__ __align__(16) float sm_m[4][NB][32];
    __shared__ __align__(16) float sm_f[4][NB][CIN];

    const int t = threadIdx.x;
    const int w = t >> 5, lane = t & 31;

    for (int i = t; i < 96; i += 128) sw0[i / 32][i % 32] = w0[i];
    if (t < 32) { sb0[t] = b0[t]; sb1[t] = b1[t]; sb2[t] = b2[t]; }
    for (int i = t; i < 1024; i += 128) {
        sw1t[i % 32][i / 32] = w1[i];
        sw2t[i % 32][i / 32] = w2[i];
    }
    __syncthreads();

    const int g = blockIdx.x * 4 + w;
    const int b = g >> 11;

    const int n  = lane >> 1;          // neighbor handled by this lane pair
    const int jb = (lane & 1) * 16;    // output half

    const int gi = g_idx[g * NB + n];

    // Full-warp feature gather: 256 float4 total, 8 per lane.
#pragma unroll
    for (int i = 0; i < 8; ++i) {
        const int ii = lane + i * 32;
        const int nn = ii >> 4, q = ii & 15;
        const int gin = __shfl_sync(0xffffffffu, gi, nn * 2);
        *(float4*)&sm_f[w][nn][q * 4] =
            *(const float4*)&feats[((size_t)b * P_ + gin) * CIN + q * 4];
    }

    // MLP (all lanes; 16 outputs each)
    const float rx = points[((size_t)b * P_ + gi) * 3 + 0] - keys[g * 3 + 0];
    const float ry = points[((size_t)b * P_ + gi) * 3 + 1] - keys[g * 3 + 1];
    const float rz = points[((size_t)b * P_ + gi) * 3 + 2] - keys[g * 3 + 2];

    float h1[16];
#pragma unroll
    for (int j = 0; j < 16; ++j) {
        const int jj = jb + j;
        h1[j] = fmaxf(fmaf(rx, sw0[0][jj], fmaf(ry, sw0[1][jj],
                      fmaf(rz, sw0[2][jj], sb0[jj]))), 0.0f);
    }
    float h1o[16];
#pragma unroll
    for (int j = 0; j < 16; ++j) h1o[j] = __shfl_xor_sync(0xffffffffu, h1[j], 1);

    float h2[16];
#pragma unroll
    for (int j = 0; j < 16; ++j) {
        const int jj = jb + j;
        float a = sb1[jj];
        const float4* wo = (const float4*)(sw1t[jj] + jb);          // own half
        const float4* wp = (const float4*)(sw1t[jj] + (jb ^ 16));   // partner half
#pragma unroll
        for (int q = 0; q < 4; ++q) {
            float4 v = wo[q];
            a = fmaf(h1[4 * q + 0], v.x, a);
            a = fmaf(h1[4 * q + 1], v.y, a);
            a = fmaf(h1[4 * q + 2], v.z, a);
            a = fmaf(h1[4 * q + 3], v.w, a);
            float4 u = wp[q];
            a = fmaf(h1o[4 * q + 0], u.x, a);
            a = fmaf(h1o[4 * q + 1], u.y, a);
            a = fmaf(h1o[4 * q + 2], u.z, a);
            a = fmaf(h1o[4 * q + 3], u.w, a);
        }
        h2[j] = fmaxf(a, 0.0f);
    }
    float h2o[16];
#pragma unroll
    for (int j = 0; j < 16; ++j) h2o[j] = __shfl_xor_sync(0xffffffffu, h2[j], 1);

#pragma unroll
    for (int j = 0; j < 16; ++j) {
        const int jj = jb + j;
        float a = sb2[jj];
        const float4* wo = (const float4*)(sw2t[jj] + jb);
        const float4* wp = (const float4*)(sw2t[jj] + (jb ^ 16));
#pragma unroll
        for (int q = 0; q < 4; ++q) {
            float4 v = wo[q];
            a = fmaf(h2[4 * q + 0], v.x, a);
            a = fmaf(h2[4 * q + 1], v.y, a);
            a = fmaf(h2[4 * q + 2], v.z, a);
            a = fmaf(h2[4 * q + 3], v.w, a);
            float4 u = wp[q];
            a = fmaf(h2o[4 * q + 0], u.x, a);
            a = fmaf(h2o[4 * q + 1], u.y, a);
            a = fmaf(h2o[4 * q + 2], u.z, a);
            a = fmaf(h2o[4 * q + 3], u.w, a);
        }
        sm_m[w][n][jj] = a;   // linear output, no relu
    }
    __syncwarp();

    // Aggregation: e[mc][c] = sum_n m[n][mc] * f[n][c]; lane owns c = 2*lane, 2*lane+1.
    float e0[32], e1[32];
#pragma unroll
    for (int j = 0; j < 32; ++j) { e0[j] = 0.0f; e1[j] = 0.0f; }

#pragma unroll
    for (int nn = 0; nn < NB; ++nn) {
        const float2 f = *(const float2*)&sm_f[w][nn][2 * lane];
        const float4* mp = (const float4*)sm_m[w][nn];
#pragma unroll
        for (int q = 0; q < 8; ++q) {
            float4 mv = mp[q];
            e0[4 * q + 0] = fmaf(mv.x, f.x, e0[4 * q + 0]);
            e1[4 * q + 0] = fmaf(mv.x, f.y, e1[4 * q + 0]);
            e0[4 * q + 1] = fmaf(mv.y, f.x, e0[4 * q + 1]);
            e1[4 * q + 1] = fmaf(mv.y, f.y, e1[4 * q + 1]);
            e0[4 * q + 2] = fmaf(mv.z, f.x, e0[4 * q + 2]);
            e1[4 * q + 2] = fmaf(mv.z, f.y, e1[4 * q + 2]);
            e0[4 * q + 3] = fmaf(mv.w, f.x, e0[4 * q + 3]);
            e1[4 * q + 3] = fmaf(mv.w, f.y, e1[4 * q + 3]);
        }
    }

    uint32_t* EhP = (uint32_t*)(g_Ehi + (size_t)g * EDIM);
    uint32_t* ElP = (uint32_t*)(g_Elo + (size_t)g * EDIM);
#pragma unroll
    for (int mc = 0; mc < 32; ++mc) {
        uint32_t lo;
        uint32_t hi = pack_split(e0[mc], e1[mc], lo);
        EhP[mc * 32 + lane] = hi;
        ElP[mc * 32 + lane] = lo;
    }
}

// ---------------------------------------------------------------------------
// Kernel 3: gemm1 HMMA — H = relu(E @ W0 + b0), 3-term bf16 split.
// NEW TILING: BM=128, BN=64, BK=64 -> grid 4x64 = 256 CTAs, 48KB/stage,
// 2 stages = 96KB -> 2 CTAs/SM. All 148 SMs active (vs 128 CTAs before) and
// cross-CTA overlap hides cp.async/sync bubbles. Warp tile 32x32 (4x2 grid),
// single-buffered fragments (round-11 proven mainloop shape).
// ---------------------------------------------------------------------------
constexpr int G1_A_BYTES = 128 * 64 * 2;      // 16384 (per A sub-tile)
constexpr int G1_B_BYTES = 64 * 64 * 2;       // 8192  (per B sub-tile)
constexpr int G1_STAGE   = 2 * G1_A_BYTES + 2 * G1_B_BYTES;   // 49152
constexpr int G1_SMEM    = 2 * G1_STAGE;      // 98304
constexpr int G1_NI      = EDIM / 64;         // 32

__global__ void __launch_bounds__(256, 2) gemm1_mma_kernel(const float* __restrict__ bias)
{
    extern __shared__ char smem[];
    const uint32_t base = smem_u32(smem);
    const int tid  = threadIdx.x;
    const int wid  = tid >> 5;
    const int lane = tid & 31;
    const int m0 = blockIdx.y * 128;
    const int n0 = blockIdx.x * 64;
    const int warpM = (wid & 3) * 32;     // 4 warps over M=128
    const int warpN = (wid >> 2) * 32;    // 2 warps over N=64

    const __nv_bfloat16* srcA_hi = g_Ehi + (size_t)m0 * EDIM;
    const __nv_bfloat16* srcA_lo = g_Elo + (size_t)m0 * EDIM;
    const __nv_bfloat16* srcB_hi = g_Whi + (size_t)n0 * EDIM;
    const __nv_bfloat16* srcB_lo = g_Wlo + (size_t)n0 * EDIM;

    auto load_stage = [&](int it) {
        const uint32_t sb = base + (it & 1) * G1_STAGE;
        const int k0 = it * 64;
        // A hi/lo: 128 rows x 64 cols = 1024 cp16 each -> 4 per thread
#pragma unroll
        for (int s = 0; s < 2; ++s) {
            const __nv_bfloat16* sp = (s == 0 ? srcA_hi : srcA_lo) + k0;
            const uint32_t sbase = sb + s * G1_A_BYTES;
#pragma unroll
            for (int j = 0; j < 4; ++j) {
                const int idx = tid + j * 256;              // 0..1023
                const int r = idx >> 3, c = idx & 7;
                const uint32_t off = (uint32_t)idx * 16;
                const uint32_t dst = sbase + (off ^ ((off >> 3) & 0x70));
                cp_async16(dst, sp + (size_t)r * EDIM + c * 8);
            }
        }
        // B hi/lo: 64 rows x 64 cols = 512 cp16 each -> 2 per thread
#pragma unroll
        for (int s = 0; s < 2; ++s) {
            const __nv_bfloat16* sp = (s == 0 ? srcB_hi : srcB_lo) + k0;
            const uint32_t sbase = sb + 2 * G1_A_BYTES + s * G1_B_BYTES;
#pragma unroll
            for (int j = 0; j < 2; ++j) {
                const int idx = tid + j * 256;              // 0..511
                const int r = idx >> 3, c = idx & 7;
                const uint32_t off = (uint32_t)idx * 16;
                const uint32_t dst = sbase + (off ^ ((off >> 3) & 0x70));
                cp_async16(dst, sp + (size_t)r * EDIM + c * 8);
            }
        }
    };

    float acc[2][4][4];
#pragma unroll
    for (int i = 0; i < 2; ++i)
#pragma unroll
        for (int j = 0; j < 4; ++j)
#pragma unroll
            for (int q = 0; q < 4; ++q) acc[i][j][q] = 0.0f;

    const int aRow = ((lane >> 3) & 1) * 8 + (lane & 7);
    const int aKof = (lane >> 4) * 8;
    const int bRow = ((lane >> 4) & 1) * 8 + (lane & 7);
    const int bKof = ((lane >> 3) & 1) * 8;

    load_stage(0);
    cp_commit();

    for (int it = 0; it < G1_NI; ++it) {
        if (it + 1 < G1_NI) {
            load_stage(it + 1);
            cp_commit();
            cp_wait<1>();
        } else {
            cp_wait<0>();
        }
        __syncthreads();

        const uint32_t sb = base + (it & 1) * G1_STAGE;
        const uint32_t sA_hi = sb;
        const uint32_t sA_lo = sb + G1_A_BYTES;
        const uint32_t sB_hi = sb + 2 * G1_A_BYTES;
        const uint32_t sB_lo = sb + 2 * G1_A_BYTES + G1_B_BYTES;

#pragma unroll
        for (int kk = 0; kk < 4; ++kk) {
            const int k0 = kk * 16;
            uint32_t ah[2][4], al[2][4], bh[2][4], bl[2][4];
#pragma unroll
            for (int mi = 0; mi < 2; ++mi) {
                const int row = warpM + mi * 16 + aRow;
                const int col = k0 + aKof;
                const uint32_t off = (uint32_t)(row * 128 + col * 2);
                const uint32_t sw  = off ^ ((off >> 3) & 0x70);
                ldm_x4(ah[mi], sA_hi + sw);
                ldm_x4(al[mi], sA_lo + sw);
            }
#pragma unroll
            for (int nj = 0; nj < 2; ++nj) {
                const int row = warpN + nj * 16 + bRow;
                const int col = k0 + bKof;
                const uint32_t off = (uint32_t)(row * 128 + col * 2);
                const uint32_t sw  = off ^ ((off >> 3) & 0x70);
                ldm_x4(bh[nj], sB_hi + sw);
                ldm_x4(bl[nj], sB_lo + sw);
            }
#pragma unroll
            for (int mi = 0; mi < 2; ++mi)
#pragma unroll
                for (int nj = 0; nj < 2; ++nj)
#pragma unroll
                    for (int nk = 0; nk < 2; ++nk) {
                        float* d = acc[mi][nj * 2 + nk];
                        mma_bf16(d, ah[mi], bh[nj][nk * 2], bh[nj][nk * 2 + 1]);
                        mma_bf16(d, ah[mi], bl[nj][nk * 2], bl[nj][nk * 2 + 1]);
                        mma_bf16(d, al[mi], bh[nj][nk * 2], bh[nj][nk * 2 + 1]);
                    }
        }
        __syncthreads();
    }

    // Epilogue: bias + relu, split to bf16 hi/lo, packed u32 stores.
#pragma unroll
    for (int mi = 0; mi < 2; ++mi) {
        const int row = m0 + warpM + mi * 16 + (lane >> 2);
#pragma unroll
        for (int ni = 0; ni < 4; ++ni) {
            const int col = n0 + warpN + ni * 8 + 2 * (lane & 3);
            const float b0v = bias[col], b1v = bias[col + 1];
            const float v0 = fmaxf(acc[mi][ni][0] + b0v, 0.0f);
            const float v1 = fmaxf(acc[mi][ni][1] + b1v, 0.0f);
            const float v2 = fmaxf(acc[mi][ni][2] + b0v, 0.0f);
            const float v3 = fmaxf(acc[mi][ni][3] + b1v, 0.0f);
            uint32_t lo01, lo23;
            const uint32_t hi01 = pack_split(v0, v1, lo01);
            const uint32_t hi23 = pack_split(v2, v3, lo23);
            ((uint32_t*)(g_Hhi + (size_t)row * FH))[col >> 1]       = hi01;
            ((uint32_t*)(g_Hlo + (size_t)row * FH))[col >> 1]       = lo01;
            ((uint32_t*)(g_Hhi + (size_t)(row + 8) * FH))[col >> 1] = hi23;
            ((uint32_t*)(g_Hlo + (size_t)(row + 8) * FH))[col >> 1] = lo23;
        }
    }
}

// ---------------------------------------------------------------------------
// Kernel 4: gemm2 HMMA — out = H @ W1 + b1, 3-term bf16 split.
// FULL PREFETCH: all 4 K-stages issued at t=0 (192KB smem), consumed with
// wait_group 3/2/1/0 — measured win (10.2 -> 9.4us); kept.
// ---------------------------------------------------------------------------
constexpr int G2_A_BYTES = 64 * 64 * 2;        // 8192
constexpr int G2_B_BYTES = 128 * 64 * 2;       // 16384
constexpr int G2_STAGE   = 2 * G2_A_BYTES + 2 * G2_B_BYTES;   // 49152
constexpr int G2_NI      = FH / 64;            // 4
constexpr int G2_SMEM    = G2_NI * G2_STAGE;   // 196608

__global__ void __launch_bounds__(256, 1) gemm2_mma_kernel(const float* __restrict__ bias,
                                                           float* __restrict__ C)
{
    extern __shared__ char smem[];
    const uint32_t base = smem_u32(smem);
    const int tid  = threadIdx.x;
    const int wid  = tid >> 5;
    const int lane = tid & 31;
    const int m0 = blockIdx.y * 64;
    const int warpM = (wid & 1) * 32;
    const int warpN = (wid >> 1) * 32;

    const __nv_bfloat16* srcA_hi = g_Hhi + (size_t)m0 * FH;
    const __nv_bfloat16* srcA_lo = g_Hlo + (size_t)m0 * FH;

    auto load_stage = [&](int it) {
        const uint32_t sb = base + it * G2_STAGE;
        const int k0 = it * 64;
#pragma unroll
        for (int s = 0; s < 2; ++s) {
            const __nv_bfloat16* sp = (s == 0 ? srcA_hi : srcA_lo) + k0;
            const uint32_t sbase = sb + s * G2_A_BYTES;
#pragma unroll
            for (int j = 0; j < 2; ++j) {
                const int idx = tid + j * 256;              // 0..511
                const int r = idx >> 3, c = idx & 7;
                const uint32_t off = (uint32_t)idx * 16;
                const uint32_t dst = sbase + (off ^ ((off >> 3) & 0x70));
                cp_async16(dst, sp + (size_t)r * FH + c * 8);
            }
        }
#pragma unroll
        for (int s = 0; s < 2; ++s) {
            const __nv_bfloat16* sp = (s == 0 ? g_W1hi : g_W1lo) + k0;
            const uint32_t sbase = sb + 2 * G2_A_BYTES + s * G2_B_BYTES;
#pragma unroll
            for (int j = 0; j < 4; ++j) {
                const int idx = tid + j * 256;              // 0..1023
                const int r = idx >> 3, c = idx & 7;
                const uint32_t off = (uint32_t)idx * 16;
                const uint32_t dst = sbase + (off ^ ((off >> 3) & 0x70));
                cp_async16(dst, sp + (size_t)r * FH + c * 8);
            }
        }
    };

    float acc[2][4][4];
#pragma unroll
    for (int i = 0; i < 2; ++i)
#pragma unroll
        for (int j = 0; j < 4; ++j)
#pragma unroll
            for (int q = 0; q < 4; ++q) acc[i][j][q] = 0.0f;

    const int aRow = ((lane >> 3) & 1) * 8 + (lane & 7);
    const int aKof = (lane >> 4) * 8;
    const int bRow = ((lane >> 4) & 1) * 8 + (lane & 7);
    const int bKof = ((lane >> 3) & 1) * 8;

    // Issue ALL stages up front.
#pragma unroll
    for (int it = 0; it < G2_NI; ++it) {
        load_stage(it);
        cp_commit();
    }

#pragma unroll
    for (int it = 0; it < G2_NI; ++it) {
        switch (G2_NI - 1 - it) {   // groups still allowed in flight
            case 3: cp_wait<3>(); break;
            case 2: cp_wait<2>(); break;
            case 1: cp_wait<1>(); break;
            default: cp_wait<0>(); break;
        }
        __syncthreads();

        const uint32_t sb = base + it * G2_STAGE;
        const uint32_t sA_hi = sb;
        const uint32_t sA_lo = sb + G2_A_BYTES;
        const uint32_t sB_hi = sb + 2 * G2_A_BYTES;
        const uint32_t sB_lo = sb + 2 * G2_A_BYTES + G2_B_BYTES;

#pragma unroll
        for (int kk = 0; kk < 4; ++kk) {
            const int k0 = kk * 16;
            uint32_t ah[2][4], al[2][4], bh[2][4], bl[2][4];
#pragma unroll
            for (int mi = 0; mi < 2; ++mi) {
                const int row = warpM + mi * 16 + aRow;
                const int col = k0 + aKof;
                const uint32_t off = (uint32_t)(row * 128 + col * 2);
                const uint32_t sw  = off ^ ((off >> 3) & 0x70);
                ldm_x4(ah[mi], sA_hi + sw);
                ldm_x4(al[mi], sA_lo + sw);
            }
#pragma unroll
            for (int nj = 0; nj < 2; ++nj) {
                const int row = warpN + nj * 16 + bRow;
                const int col = k0 + bKof;
                const uint32_t off = (uint32_t)(row * 128 + col * 2);
                const uint32_t sw  = off ^ ((off >> 3) & 0x70);
                ldm_x4(bh[nj], sB_hi + sw);
                ldm_x4(bl[nj], sB_lo + sw);
            }
#pragma unroll
            for (int mi = 0; mi < 2; ++mi)
#pragma unroll
                for (int nj = 0; nj < 2; ++nj)
#pragma unroll
                    for (int nk = 0; nk < 2; ++nk) {
                        float* d = acc[mi][nj * 2 + nk];
                        mma_bf16(d, ah[mi], bh[nj][nk * 2], bh[nj][nk * 2 + 1]);
                        mma_bf16(d, ah[mi], bl[nj][nk * 2], bl[nj][nk * 2 + 1]);
                        mma_bf16(d, al[mi], bh[nj][nk * 2], bh[nj][nk * 2 + 1]);
                    }
        }
    }

    // Epilogue: bias, fp32 out (no relu)
#pragma unroll
    for (int mi = 0; mi < 2; ++mi) {
        const int row = m0 + warpM + mi * 16 + (lane >> 2);
#pragma unroll
        for (int ni = 0; ni < 4; ++ni) {
            const int col = warpN + ni * 8 + 2 * (lane & 3);
            const float b0v = bias[col], b1v = bias[col + 1];
            float2 v0, v1;
            v0.x = acc[mi][ni][0] + b0v;
            v0.y = acc[mi][ni][1] + b1v;
            v1.x = acc[mi][ni][2] + b0v;
            v1.y = acc[mi][ni][3] + b1v;
            *(float2*)&C[(size_t)row * COUT + col]       = v0;
            *(float2*)&C[(size_t)(row + 8) * COUT + col] = v1;
        }
    }
}

// ---------------------------------------------------------------------------
extern "C" void kernel_launch(void* const* d_in, const int* in_sizes, int n_in,
                              void* d_out, int out_size)
{
    const float* keys   = (const float*)d_in[0];
    const float* points = (const float*)d_in[1];
    const float* feats  = (const float*)d_in[2];
    const float* wc0W   = (const float*)d_in[3];
    const float* wc0b   = (const float*)d_in[4];
    const float* wc1W   = (const float*)d_in[5];
    const float* wc1b   = (const float*)d_in[6];
    const float* wc2W   = (const float*)d_in[7];
    const float* wc2b   = (const float*)d_in[8];
    const float* fc0W   = (const float*)d_in[9];
    const float* fc0b   = (const float*)d_in[10];
    const float* fc1W   = (const float*)d_in[11];
    const float* fc1b   = (const float*)d_in[12];
    float* out = (float*)d_out;

    cudaFuncSetAttribute(gemm1_mma_kernel,
                         cudaFuncAttributeMaxDynamicSharedMemorySize, G1_SMEM);
    cudaFuncSetAttribute(gemm2_mma_kernel,
                         cudaFuncAttributeMaxDynamicSharedMemorySize, G2_SMEM);

    knn_prep_kernel<<<640 + GK / 16, 256>>>(keys, points, fc0W, fc1W);
    edge_kernel<<<GK / 4, 128>>>(keys, points, feats,
                                 wc0W, wc0b, wc1W, wc1b, wc2W, wc2b);
    gemm1_mma_kernel<<<dim3(FH / 64, GK / 128), 256, G1_SMEM>>>(fc0b);
    gemm2_mma_kernel<<<dim3(1, GK / 64), 256, G2_SMEM>>>(fc1b, out);
}

// round 15
// speedup vs baseline: 1.0348x; 1.0348x over previous
#include <cuda_runtime.h>
#include <cuda_bf16.h>
#include <cstdint>

#define DEV_INLINE __device__ __forceinline__

constexpr int B_   = 4;
constexpr int K_   = 2048;
constexpr int P_   = 4096;
constexpr int NB   = 16;
constexpr int CIN  = 64;
constexpr int CMID = 32;
constexpr int FH   = 256;
constexpr int COUT = 128;
constexpr int GK   = B_ * K_;        // 8192 keys total
constexpr int EDIM = CMID * CIN;     // 2048

// Scratch (allocation-free rule: __device__ globals)
__device__ int            g_idx[GK * NB];
__device__ __nv_bfloat16  g_Ehi[(size_t)GK * EDIM];   // 32 MB
__device__ __nv_bfloat16  g_Elo[(size_t)GK * EDIM];   // 32 MB
__device__ __nv_bfloat16  g_Whi[(size_t)FH * EDIM];   // W0^T split, [256][2048]
__device__ __nv_bfloat16  g_Wlo[(size_t)FH * EDIM];
__device__ __nv_bfloat16  g_Hhi[(size_t)GK * FH];     // H split, [8192][256]
__device__ __nv_bfloat16  g_Hlo[(size_t)GK * FH];
__device__ __nv_bfloat16  g_W1hi[COUT * FH];          // W1^T split, [128][256]
__device__ __nv_bfloat16  g_W1lo[COUT * FH];

// ---------------------------------------------------------------------------
// PTX helpers (cp.async / ldmatrix / mma.sync — baseline sm_80+, plain sm_103 OK)
// ---------------------------------------------------------------------------
DEV_INLINE uint32_t smem_u32(const void* p) {
    return (uint32_t)__cvta_generic_to_shared(p);
}

DEV_INLINE void cp_async16(uint32_t dst, const void* src) {
    asm volatile("cp.async.cg.shared.global [%0], [%1], 16;"
                 :: "r"(dst), "l"(src) : "memory");
}
DEV_INLINE void cp_commit()  { asm volatile("cp.async.commit_group;" ::: "memory"); }
template <int N> DEV_INLINE void cp_wait() {
    asm volatile("cp.async.wait_group %0;" :: "n"(N) : "memory");
}

DEV_INLINE void ldm_x4(uint32_t* r, uint32_t addr) {
    asm volatile("ldmatrix.sync.aligned.m8n8.x4.shared.b16 {%0,%1,%2,%3}, [%4];"
                 : "=r"(r[0]), "=r"(r[1]), "=r"(r[2]), "=r"(r[3]) : "r"(addr));
}

DEV_INLINE void mma_bf16(float* d, const uint32_t* a, uint32_t b0, uint32_t b1) {
    asm volatile(
        "mma.sync.aligned.m16n8k16.row.col.f32.bf16.bf16.f32 "
        "{%0,%1,%2,%3}, {%4,%5,%6,%7}, {%8,%9}, {%0,%1,%2,%3};"
        : "+f"(d[0]), "+f"(d[1]), "+f"(d[2]), "+f"(d[3])
        : "r"(a[0]), "r"(a[1]), "r"(a[2]), "r"(a[3]), "r"(b0), "r"(b1));
}

// Split v0,v1 into bf16 hi (returned packed) and bf16 lo (out-param packed).
DEV_INLINE uint32_t pack_split(float v0, float v1, uint32_t& lo_out) {
    __nv_bfloat16 h0 = __float2bfloat16(v0);
    __nv_bfloat16 h1 = __float2bfloat16(v1);
    __nv_bfloat16 l0 = __float2bfloat16(v0 - __bfloat162float(h0));
    __nv_bfloat16 l1 = __float2bfloat16(v1 - __bfloat162float(h1));
    lo_out = ((uint32_t)__bfloat16_as_ushort(l1) << 16) | __bfloat16_as_ushort(l0);
    return ((uint32_t)__bfloat16_as_ushort(h1) << 16) | __bfloat16_as_ushort(h0);
}

// ---------------------------------------------------------------------------
// Kernel 1: fused prep + KNN (round-11 verified form: 8 keys/block, 1/warp).
// Blocks 0..511:  W0 transpose-split. Blocks 512..639: W1 split.
// Blocks 640..1663: KNN (warp-wide distributed top-16).
// ---------------------------------------------------------------------------
__global__ void __launch_bounds__(256) knn_prep_kernel(
    const float* __restrict__ keys, const float* __restrict__ points,
    const float* __restrict__ W0, const float* __restrict__ W1)
{
    __shared__ float sp[P_ * 3];   // 48KB: points tile for knn / transpose tile for prep
    const int bx = blockIdx.x;

    if (bx < 512) {
        // --- W0 transpose-split ---
        float (*tile)[33] = (float(*)[33])sp;
        const int tx = threadIdx.x & 31, ty = threadIdx.x >> 5;
        const int k0 = (bx & 63) * 32, n0 = (bx >> 6) * 32;
#pragma unroll
        for (int i = 0; i < 4; ++i)
            tile[ty + i * 8][tx] = W0[(size_t)(k0 + ty + i * 8) * FH + n0 + tx];
        __syncthreads();
#pragma unroll
        for (int i = 0; i < 4; ++i) {
            const int nn = n0 + ty + i * 8, kk = k0 + tx;
            const float v = tile[tx][ty + i * 8];
            __nv_bfloat16 h = __float2bfloat16(v);
            g_Whi[(size_t)nn * EDIM + kk] = h;
            g_Wlo[(size_t)nn * EDIM + kk] = __float2bfloat16(v - __bfloat162float(h));
        }
        return;
    }
    if (bx < 640) {
        // --- W1 split ---
        const int idx = (bx - 512) * 256 + threadIdx.x;   // 0..32767
        const int nn = idx >> 8, kk = idx & 255;
        const float v = W1[kk * COUT + nn];
        __nv_bfloat16 h = __float2bfloat16(v);
        g_W1hi[nn * FH + kk] = h;
        g_W1lo[nn * FH + kk] = __float2bfloat16(v - __bfloat162float(h));
        return;
    }

    // --- KNN: 8 keys per block, 1 key per warp ---
    const int kb = bx - 640;
    const int warp = threadIdx.x >> 5;
    const int lane = threadIdx.x & 31;
    const int g = kb * 8 + warp;
    const int b = g >> 11;
    const unsigned FULL = 0xffffffffu;

    const float* pb = points + (size_t)b * P_ * 3;
    for (int i = threadIdx.x; i < P_ * 3; i += 256) sp[i] = pb[i];
    __syncthreads();

    const float kx = keys[g * 3 + 0];
    const float ky = keys[g * 3 + 1];
    const float kz = keys[g * 3 + 2];

    float ld = 3.4e38f;          // distributed list entry (lanes 0..15 valid)
    int   li = 0x7fffffff;
    float warpMax = 3.4e38f;     // current 16th smallest (uniform)

    for (int p = lane; p < P_; p += 32) {
        float dx = __fsub_rn(sp[p * 3 + 0], kx);
        float dy = __fsub_rn(sp[p * 3 + 1], ky);
        float dz = __fsub_rn(sp[p * 3 + 2], kz);
        float d  = __fadd_rn(__fadd_rn(__fmul_rn(dx, dx), __fmul_rn(dy, dy)),
                             __fmul_rn(dz, dz));

        unsigned hit = __ballot_sync(FULL, d < warpMax);
        while (hit) {
            const int src = __ffs(hit) - 1;
            hit &= hit - 1;
            const float dc = __shfl_sync(FULL, d, src);
            const int   ic = __shfl_sync(FULL, p, src);
            if (dc < warpMax) {   // recheck: warpMax tightens within this loop
                const unsigned bal =
                    __ballot_sync(FULL, (lane < NB) && (ld <= dc));
                const int pos = __popc(bal);
                const float pd = __shfl_up_sync(FULL, ld, 1);
                const int   pi = __shfl_up_sync(FULL, li, 1);
                if (lane >= pos && lane < NB) {
                    ld = (lane == pos) ? dc : pd;
                    li = (lane == pos) ? ic : pi;
                }
                warpMax = __shfl_sync(FULL, ld, NB - 1);
            }
        }
    }
    if (lane < NB) g_idx[g * NB + lane] = li;
}

// ---------------------------------------------------------------------------
// Kernel 2: per-edge weight MLP + aggregation -> E (bf16 hi/lo, packed stores).
// (verified; unchanged)
// ---------------------------------------------------------------------------
__global__ void __launch_bounds__(128) edge_kernel(
    const float* __restrict__ keys, const float* __restrict__ points,
    const float* __restrict__ feats,
    const float* __restrict__ w0, const float* __restrict__ b0,
    const float* __restrict__ w1, const float* __restrict__ b1,
    const float* __restrict__ w2, const float* __restrict__ b2)
{
    __shared__ __align__(16) float sw0[3][32];
    __shared__ float sb0[32], sb1[32], sb2[32];
    __shared__ __align__(16) float sw1t[32][32];   // [out][in]
    __shared__ __align__(16) float sw2t[32][32];
    __shared__ __align__(16) float sm_m[4][NB][32];
    __shared__ __align__(16) float sm_f[4][NB][CIN];

    const int t = threadIdx.x;
    const int w = t >> 5, lane = t & 31;

    for (int i = t; i < 96; i += 128) sw0[i / 32][i % 32] = w0[i];
    if (t < 32) { sb0[t] = b0[t]; sb1[t] = b1[t]; sb2[t] = b2[t]; }
    for (int i = t; i < 1024; i += 128) {
        sw1t[i % 32][i / 32] = w1[i];
        sw2t[i % 32][i / 32] = w2[i];
    }
    __syncthreads();

    const int g = blockIdx.x * 4 + w;
    const int b = g >> 11;

    const int n  = lane >> 1;          // neighbor handled by this lane pair
    const int jb = (lane & 1) * 16;    // output half

    const int gi = g_idx[g * NB + n];

    // Full-warp feature gather: 256 float4 total, 8 per lane.
#pragma unroll
    for (int i = 0; i < 8; ++i) {
        const int ii = lane + i * 32;
        const int nn = ii >> 4, q = ii & 15;
        const int gin = __shfl_sync(0xffffffffu, gi, nn * 2);
        *(float4*)&sm_f[w][nn][q * 4] =
            *(const float4*)&feats[((size_t)b * P_ + gin) * CIN + q * 4];
    }

    // MLP (all lanes; 16 outputs each)
    const float rx = points[((size_t)b * P_ + gi) * 3 + 0] - keys[g * 3 + 0];
    const float ry = points[((size_t)b * P_ + gi) * 3 + 1] - keys[g * 3 + 1];
    const float rz = points[((size_t)b * P_ + gi) * 3 + 2] - keys[g * 3 + 2];

    float h1[16];
#pragma unroll
    for (int j = 0; j < 16; ++j) {
        const int jj = jb + j;
        h1[j] = fmaxf(fmaf(rx, sw0[0][jj], fmaf(ry, sw0[1][jj],
                      fmaf(rz, sw0[2][jj], sb0[jj]))), 0.0f);
    }
    float h1o[16];
#pragma unroll
    for (int j = 0; j < 16; ++j) h1o[j] = __shfl_xor_sync(0xffffffffu, h1[j], 1);

    float h2[16];
#pragma unroll
    for (int j = 0; j < 16; ++j) {
        const int jj = jb + j;
        float a = sb1[jj];
        const float4* wo = (const float4*)(sw1t[jj] + jb);          // own half
        const float4* wp = (const float4*)(sw1t[jj] + (jb ^ 16));   // partner half
#pragma unroll
        for (int q = 0; q < 4; ++q) {
            float4 v = wo[q];
            a = fmaf(h1[4 * q + 0], v.x, a);
            a = fmaf(h1[4 * q + 1], v.y, a);
            a = fmaf(h1[4 * q + 2], v.z, a);
            a = fmaf(h1[4 * q + 3], v.w, a);
            float4 u = wp[q];
            a = fmaf(h1o[4 * q + 0], u.x, a);
            a = fmaf(h1o[4 * q + 1], u.y, a);
            a = fmaf(h1o[4 * q + 2], u.z, a);
            a = fmaf(h1o[4 * q + 3], u.w, a);
        }
        h2[j] = fmaxf(a, 0.0f);
    }
    float h2o[16];
#pragma unroll
    for (int j = 0; j < 16; ++j) h2o[j] = __shfl_xor_sync(0xffffffffu, h2[j], 1);

#pragma unroll
    for (int j = 0; j < 16; ++j) {
        const int jj = jb + j;
        float a = sb2[jj];
        const float4* wo = (const float4*)(sw2t[jj] + jb);
        const float4* wp = (const float4*)(sw2t[jj] + (jb ^ 16));
#pragma unroll
        for (int q = 0; q < 4; ++q) {
            float4 v = wo[q];
            a = fmaf(h2[4 * q + 0], v.x, a);
            a = fmaf(h2[4 * q + 1], v.y, a);
            a = fmaf(h2[4 * q + 2], v.z, a);
            a = fmaf(h2[4 * q + 3], v.w, a);
            float4 u = wp[q];
            a = fmaf(h2o[4 * q + 0], u.x, a);
            a = fmaf(h2o[4 * q + 1], u.y, a);
            a = fmaf(h2o[4 * q + 2], u.z, a);
            a = fmaf(h2o[4 * q + 3], u.w, a);
        }
        sm_m[w][n][jj] = a;   // linear output, no relu
    }
    __syncwarp();

    // Aggregation: e[mc][c] = sum_n m[n][mc] * f[n][c]; lane owns c = 2*lane, 2*lane+1.
    float e0[32], e1[32];
#pragma unroll
    for (int j = 0; j < 32; ++j) { e0[j] = 0.0f; e1[j] = 0.0f; }

#pragma unroll
    for (int nn = 0; nn < NB; ++nn) {
        const float2 f = *(const float2*)&sm_f[w][nn][2 * lane];
        const float4* mp = (const float4*)sm_m[w][nn];
#pragma unroll
        for (int q = 0; q < 8; ++q) {
            float4 mv = mp[q];
            e0[4 * q + 0] = fmaf(mv.x, f.x, e0[4 * q + 0]);
            e1[4 * q + 0] = fmaf(mv.x, f.y, e1[4 * q + 0]);
            e0[4 * q + 1] = fmaf(mv.y, f.x, e0[4 * q + 1]);
            e1[4 * q + 1] = fmaf(mv.y, f.y, e1[4 * q + 1]);
            e0[4 * q + 2] = fmaf(mv.z, f.x, e0[4 * q + 2]);
            e1[4 * q + 2] = fmaf(mv.z, f.y, e1[4 * q + 2]);
            e0[4 * q + 3] = fmaf(mv.w, f.x, e0[4 * q + 3]);
            e1[4 * q + 3] = fmaf(mv.w, f.y, e1[4 * q + 3]);
        }
    }

    uint32_t* EhP = (uint32_t*)(g_Ehi + (size_t)g * EDIM);
    uint32_t* ElP = (uint32_t*)(g_Elo + (size_t)g * EDIM);
#pragma unroll
    for (int mc = 0; mc < 32; ++mc) {
        uint32_t lo;
        uint32_t hi = pack_split(e0[mc], e1[mc], lo);
        EhP[mc * 32 + lane] = hi;
        ElP[mc * 32 + lane] = lo;
    }
}

// ---------------------------------------------------------------------------
// Kernel 3: gemm1 HMMA — H = relu(E @ W0 + b0), 3-term bf16 split, 128x128,
// BK=64, 3-stage cp.async pipeline, single-buffered fragments.
// (round-11 verified form — part of the 186.8us best; unchanged)
// ---------------------------------------------------------------------------
constexpr int G1_STAGE  = 4 * 16384;          // Ahi, Alo, Bhi, Blo (64KB)
constexpr int G1_STAGES = 3;
constexpr int G1_SMEM   = G1_STAGES * G1_STAGE;   // 196608
constexpr int G1_NI     = EDIM / 64;          // 32

__global__ void __launch_bounds__(256, 1) gemm1_mma_kernel(const float* __restrict__ bias)
{
    extern __shared__ char smem[];
    const uint32_t base = smem_u32(smem);
    const int tid  = threadIdx.x;
    const int wid  = tid >> 5;
    const int lane = tid & 31;
    const int m0 = blockIdx.y * 128;
    const int n0 = blockIdx.x * 128;
    const int warpM = (wid & 1) * 64;
    const int warpN = (wid >> 1) * 32;

    const __nv_bfloat16* srcA_hi = g_Ehi + (size_t)m0 * EDIM;
    const __nv_bfloat16* srcA_lo = g_Elo + (size_t)m0 * EDIM;
    const __nv_bfloat16* srcB_hi = g_Whi + (size_t)n0 * EDIM;
    const __nv_bfloat16* srcB_lo = g_Wlo + (size_t)n0 * EDIM;

    auto load_stage = [&](int it, int slot) {
        const uint32_t sb = base + slot * G1_STAGE;
        const int k0 = it * 64;
        const __nv_bfloat16* srcs[4] = {srcA_hi, srcA_lo, srcB_hi, srcB_lo};
#pragma unroll
        for (int sub = 0; sub < 4; ++sub) {
            const __nv_bfloat16* sp = srcs[sub] + k0;
            const uint32_t sbase = sb + sub * 16384;
#pragma unroll
            for (int j = 0; j < 4; ++j) {
                const int idx = tid + j * 256;
                const int r = idx >> 3, c = idx & 7;
                const uint32_t off = (uint32_t)idx * 16;
                const uint32_t dst = sbase + (off ^ ((off >> 3) & 0x70));
                cp_async16(dst, sp + (size_t)r * EDIM + c * 8);
            }
        }
    };

    float acc[4][4][4];
#pragma unroll
    for (int i = 0; i < 4; ++i)
#pragma unroll
        for (int j = 0; j < 4; ++j)
#pragma unroll
            for (int q = 0; q < 4; ++q) acc[i][j][q] = 0.0f;

    const int aRow = ((lane >> 3) & 1) * 8 + (lane & 7);
    const int aKof = (lane >> 4) * 8;
    const int bRow = ((lane >> 4) & 1) * 8 + (lane & 7);
    const int bKof = ((lane >> 3) & 1) * 8;

    load_stage(0, 0);
    cp_commit();
    load_stage(1, 1);
    cp_commit();

    int cslot = 0;   // slot holding stage `it`
    int lslot = 2;   // slot to load stage `it+2` into

    for (int it = 0; it < G1_NI; ++it) {
        if (it == G1_NI - 1) cp_wait<0>(); else cp_wait<1>();
        __syncthreads();   // all warps past compute(it-1); slot lslot reusable

        if (it + 2 < G1_NI) {
            load_stage(it + 2, lslot);
            cp_commit();
            if (++lslot == G1_STAGES) lslot = 0;
        }

        const uint32_t sb = base + cslot * G1_STAGE;
        if (++cslot == G1_STAGES) cslot = 0;
        const uint32_t sA_hi = sb;
        const uint32_t sA_lo = sb + 16384;
        const uint32_t sB_hi = sb + 32768;
        const uint32_t sB_lo = sb + 49152;

#pragma unroll
        for (int kk = 0; kk < 4; ++kk) {
            const int k0 = kk * 16;
            uint32_t ah[4][4], al[4][4], bh[2][4], bl[2][4];
#pragma unroll
            for (int mi = 0; mi < 4; ++mi) {
                const int row = warpM + mi * 16 + aRow;
                const int col = k0 + aKof;
                const uint32_t off = (uint32_t)(row * 128 + col * 2);
                const uint32_t sw  = off ^ ((off >> 3) & 0x70);
                ldm_x4(ah[mi], sA_hi + sw);
                ldm_x4(al[mi], sA_lo + sw);
            }
#pragma unroll
            for (int nj = 0; nj < 2; ++nj) {
                const int row = warpN + nj * 16 + bRow;
                const int col = k0 + bKof;
                const uint32_t off = (uint32_t)(row * 128 + col * 2);
                const uint32_t sw  = off ^ ((off >> 3) & 0x70);
                ldm_x4(bh[nj], sB_hi + sw);
                ldm_x4(bl[nj], sB_lo + sw);
            }
#pragma unroll
            for (int mi = 0; mi < 4; ++mi)
#pragma unroll
                for (int nj = 0; nj < 2; ++nj)
#pragma unroll
                    for (int nk = 0; nk < 2; ++nk) {
                        float* d = acc[mi][nj * 2 + nk];
                        mma_bf16(d, ah[mi], bh[nj][nk * 2], bh[nj][nk * 2 + 1]);
                        mma_bf16(d, ah[mi], bl[nj][nk * 2], bl[nj][nk * 2 + 1]);
                        mma_bf16(d, al[mi], bh[nj][nk * 2], bh[nj][nk * 2 + 1]);
                    }
        }
    }

    // Epilogue: bias + relu, split to bf16 hi/lo, packed u32 stores.
#pragma unroll
    for (int mi = 0; mi < 4; ++mi) {
        const int row = m0 + warpM + mi * 16 + (lane >> 2);
#pragma unroll
        for (int ni = 0; ni < 4; ++ni) {
            const int col = n0 + warpN + ni * 8 + 2 * (lane & 3);
            const float b0v = bias[col], b1v = bias[col + 1];
            const float v0 = fmaxf(acc[mi][ni][0] + b0v, 0.0f);
            const float v1 = fmaxf(acc[mi][ni][1] + b1v, 0.0f);
            const float v2 = fmaxf(acc[mi][ni][2] + b0v, 0.0f);
            const float v3 = fmaxf(acc[mi][ni][3] + b1v, 0.0f);
            uint32_t lo01, lo23;
            const uint32_t hi01 = pack_split(v0, v1, lo01);
            const uint32_t hi23 = pack_split(v2, v3, lo23);
            ((uint32_t*)(g_Hhi + (size_t)row * FH))[col >> 1]       = hi01;
            ((uint32_t*)(g_Hlo + (size_t)row * FH))[col >> 1]       = lo01;
            ((uint32_t*)(g_Hhi + (size_t)(row + 8) * FH))[col >> 1] = hi23;
            ((uint32_t*)(g_Hlo + (size_t)(row + 8) * FH))[col >> 1] = lo23;
        }
    }
}

// ---------------------------------------------------------------------------
// Kernel 4: gemm2 HMMA — out = H @ W1 + b1, 3-term bf16 split.
// FULL PREFETCH: all 4 K-stages issued at t=0 (192KB smem), consumed with
// wait_group 3/2/1/0 — measured win (10.2 -> 9.1us across two captures).
// ---------------------------------------------------------------------------
constexpr int G2_A_BYTES = 64 * 64 * 2;        // 8192
constexpr int G2_B_BYTES = 128 * 64 * 2;       // 16384
constexpr int G2_STAGE   = 2 * G2_A_BYTES + 2 * G2_B_BYTES;   // 49152
constexpr int G2_NI      = FH / 64;            // 4
constexpr int G2_SMEM    = G2_NI * G2_STAGE;   // 196608

__global__ void __launch_bounds__(256, 1) gemm2_mma_kernel(const float* __restrict__ bias,
                                                           float* __restrict__ C)
{
    extern __shared__ char smem[];
    const uint32_t base = smem_u32(smem);
    const int tid  = threadIdx.x;
    const int wid  = tid >> 5;
    const int lane = tid & 31;
    const int m0 = blockIdx.y * 64;
    const int warpM = (wid & 1) * 32;
    const int warpN = (wid >> 1) * 32;

    const __nv_bfloat16* srcA_hi = g_Hhi + (size_t)m0 * FH;
    const __nv_bfloat16* srcA_lo = g_Hlo + (size_t)m0 * FH;

    auto load_stage = [&](int it) {
        const uint32_t sb = base + it * G2_STAGE;
        const int k0 = it * 64;
#pragma unroll
        for (int s = 0; s < 2; ++s) {
            const __nv_bfloat16* sp = (s == 0 ? srcA_hi : srcA_lo) + k0;
            const uint32_t sbase = sb + s * G2_A_BYTES;
#pragma unroll
            for (int j = 0; j < 2; ++j) {
                const int idx = tid + j * 256;              // 0..511
                const int r = idx >> 3, c = idx & 7;
                const uint32_t off = (uint32_t)idx * 16;
                const uint32_t dst = sbase + (off ^ ((off >> 3) & 0x70));
                cp_async16(dst, sp + (size_t)r * FH + c * 8);
            }
        }
#pragma unroll
        for (int s = 0; s < 2; ++s) {
            const __nv_bfloat16* sp = (s == 0 ? g_W1hi : g_W1lo) + k0;
            const uint32_t sbase = sb + 2 * G2_A_BYTES + s * G2_B_BYTES;
#pragma unroll
            for (int j = 0; j < 4; ++j) {
                const int idx = tid + j * 256;              // 0..1023
                const int r = idx >> 3, c = idx & 7;
                const uint32_t off = (uint32_t)idx * 16;
                const uint32_t dst = sbase + (off ^ ((off >> 3) & 0x70));
                cp_async16(dst, sp + (size_t)r * FH + c * 8);
            }
        }
    };

    float acc[2][4][4];
#pragma unroll
    for (int i = 0; i < 2; ++i)
#pragma unroll
        for (int j = 0; j < 4; ++j)
#pragma unroll
            for (int q = 0; q < 4; ++q) acc[i][j][q] = 0.0f;

    const int aRow = ((lane >> 3) & 1) * 8 + (lane & 7);
    const int aKof = (lane >> 4) * 8;
    const int bRow = ((lane >> 4) & 1) * 8 + (lane & 7);
    const int bKof = ((lane >> 3) & 1) * 8;

    // Issue ALL stages up front.
#pragma unroll
    for (int it = 0; it < G2_NI; ++it) {
        load_stage(it);
        cp_commit();
    }

#pragma unroll
    for (int it = 0; it < G2_NI; ++it) {
        switch (G2_NI - 1 - it) {   // groups still allowed in flight
            case 3: cp_wait<3>(); break;
            case 2: cp_wait<2>(); break;
            case 1: cp_wait<1>(); break;
            default: cp_wait<0>(); break;
        }
        __syncthreads();

        const uint32_t sb = base + it * G2_STAGE;
        const uint32_t sA_hi = sb;
        const uint32_t sA_lo = sb + G2_A_BYTES;
        const uint32_t sB_hi = sb + 2 * G2_A_BYTES;
        const uint32_t sB_lo = sb + 2 * G2_A_BYTES + G2_B_BYTES;

#pragma unroll
        for (int kk = 0; kk < 4; ++kk) {
            const int k0 = kk * 16;
            uint32_t ah[2][4], al[2][4], bh[2][4], bl[2][4];
#pragma unroll
            for (int mi = 0; mi < 2; ++mi) {
                const int row = warpM + mi * 16 + aRow;
                const int col = k0 + aKof;
                const uint32_t off = (uint32_t)(row * 128 + col * 2);
                const uint32_t sw  = off ^ ((off >> 3) & 0x70);
                ldm_x4(ah[mi], sA_hi + sw);
                ldm_x4(al[mi], sA_lo + sw);
            }
#pragma unroll
            for (int nj = 0; nj < 2; ++nj) {
                const int row = warpN + nj * 16 + bRow;
                const int col = k0 + bKof;
                const uint32_t off = (uint32_t)(row * 128 + col * 2);
                const uint32_t sw  = off ^ ((off >> 3) & 0x70);
                ldm_x4(bh[nj], sB_hi + sw);
                ldm_x4(bl[nj], sB_lo + sw);
            }
#pragma unroll
            for (int mi = 0; mi < 2; ++mi)
#pragma unroll
                for (int nj = 0; nj < 2; ++nj)
#pragma unroll
                    for (int nk = 0; nk < 2; ++nk) {
                        float* d = acc[mi][nj * 2 + nk];
                        mma_bf16(d, ah[mi], bh[nj][nk * 2], bh[nj][nk * 2 + 1]);
                        mma_bf16(d, ah[mi], bl[nj][nk * 2], bl[nj][nk * 2 + 1]);
                        mma_bf16(d, al[mi], bh[nj][nk * 2], bh[nj][nk * 2 + 1]);
                    }
        }
    }

    // Epilogue: bias, fp32 out (no relu)
#pragma unroll
    for (int mi = 0; mi < 2; ++mi) {
        const int row = m0 + warpM + mi * 16 + (lane >> 2);
#pragma unroll
        for (int ni = 0; ni < 4; ++ni) {
            const int col = warpN + ni * 8 + 2 * (lane & 3);
            const float b0v = bias[col], b1v = bias[col + 1];
            float2 v0, v1;
            v0.x = acc[mi][ni][0] + b0v;
            v0.y = acc[mi][ni][1] + b1v;
            v1.x = acc[mi][ni][2] + b0v;
            v1.y = acc[mi][ni][3] + b1v;
            *(float2*)&C[(size_t)row * COUT + col]       = v0;
            *(float2*)&C[(size_t)(row + 8) * COUT + col] = v1;
        }
    }
}

// ---------------------------------------------------------------------------
extern "C" void kernel_launch(void* const* d_in, const int* in_sizes, int n_in,
                              void* d_out, int out_size)
{
    const float* keys   = (const float*)d_in[0];
    const float* points = (const float*)d_in[1];
    const float* feats  = (const float*)d_in[2];
    const float* wc0W   = (const float*)d_in[3];
    const float* wc0b   = (const float*)d_in[4];
    const float* wc1W   = (const float*)d_in[5];
    const float* wc1b   = (const float*)d_in[6];
    const float* wc2W   = (const float*)d_in[7];
    const float* wc2b   = (const float*)d_in[8];
    const float* fc0W   = (const float*)d_in[9];
    const float* fc0b   = (const float*)d_in[10];
    const float* fc1W   = (const float*)d_in[11];
    const float* fc1b   = (const float*)d_in[12];
    float* out = (float*)d_out;

    cudaFuncSetAttribute(gemm1_mma_kernel,
                         cudaFuncAttributeMaxDynamicSharedMemorySize, G1_SMEM);
    cudaFuncSetAttribute(gemm2_mma_kernel,
                         cudaFuncAttributeMaxDynamicSharedMemorySize, G2_SMEM);

    knn_prep_kernel<<<640 + GK / 8, 256>>>(keys, points, fc0W, fc1W);
    edge_kernel<<<GK / 4, 128>>>(keys, points, feats,
                                 wc0W, wc0b, wc1W, wc1b, wc2W, wc2b);
    gemm1_mma_kernel<<<dim3(FH / 128, GK / 128), 256, G1_SMEM>>>(fc0b);
    gemm2_mma_kernel<<<dim3(1, GK / 64), 256, G2_SMEM>>>(fc1b, out);
}

// round 16
// speedup vs baseline: 1.1287x; 1.0907x over previous
#include <cuda_runtime.h>
#include <cuda_bf16.h>
#include <cstdint>

#define DEV_INLINE __device__ __forceinline__

constexpr int B_   = 4;
constexpr int K_   = 2048;
constexpr int P_   = 4096;
constexpr int NB   = 16;
constexpr int CIN  = 64;
constexpr int CMID = 32;
constexpr int FH   = 256;
constexpr int COUT = 128;
constexpr int GK   = B_ * K_;        // 8192 keys total
constexpr int EDIM = CMID * CIN;     // 2048

// Scratch (allocation-free rule: __device__ globals)
__device__ int            g_idx[GK * NB];
__device__ __nv_bfloat16  g_Ehi[(size_t)GK * EDIM];   // 32 MB
__device__ __nv_bfloat16  g_Elo[(size_t)GK * EDIM];   // 32 MB
__device__ __nv_bfloat16  g_Whi[(size_t)FH * EDIM];   // W0^T split, [256][2048]
__device__ __nv_bfloat16  g_Wlo[(size_t)FH * EDIM];
__device__ __nv_bfloat16  g_Hhi[(size_t)GK * FH];     // H split, [8192][256]
__device__ __nv_bfloat16  g_Hlo[(size_t)GK * FH];
__device__ __nv_bfloat16  g_W1hi[COUT * FH];          // W1^T split, [128][256]
__device__ __nv_bfloat16  g_W1lo[COUT * FH];

// ---------------------------------------------------------------------------
// PTX helpers (cp.async / ldmatrix / mma.sync / fma.f32x2 — all compile for
// plain .target sm_103)
// ---------------------------------------------------------------------------
DEV_INLINE uint32_t smem_u32(const void* p) {
    return (uint32_t)__cvta_generic_to_shared(p);
}

DEV_INLINE void cp_async16(uint32_t dst, const void* src) {
    asm volatile("cp.async.cg.shared.global [%0], [%1], 16;"
                 :: "r"(dst), "l"(src) : "memory");
}
DEV_INLINE void cp_commit()  { asm volatile("cp.async.commit_group;" ::: "memory"); }
template <int N> DEV_INLINE void cp_wait() {
    asm volatile("cp.async.wait_group %0;" :: "n"(N) : "memory");
}

DEV_INLINE void ldm_x4(uint32_t* r, uint32_t addr) {
    asm volatile("ldmatrix.sync.aligned.m8n8.x4.shared.b16 {%0,%1,%2,%3}, [%4];"
                 : "=r"(r[0]), "=r"(r[1]), "=r"(r[2]), "=r"(r[3]) : "r"(addr));
}

DEV_INLINE void mma_bf16(float* d, const uint32_t* a, uint32_t b0, uint32_t b1) {
    asm volatile(
        "mma.sync.aligned.m16n8k16.row.col.f32.bf16.bf16.f32 "
        "{%0,%1,%2,%3}, {%4,%5,%6,%7}, {%8,%9}, {%0,%1,%2,%3};"
        : "+f"(d[0]), "+f"(d[1]), "+f"(d[2]), "+f"(d[3])
        : "r"(a[0]), "r"(a[1]), "r"(a[2]), "r"(a[3]), "r"(b0), "r"(b1));
}

// Packed fp32x2 FMA helpers (2x fp32 FMA rate; ptxas never auto-emits FFMA2)
DEV_INLINE unsigned long long splat2(float x) {
    unsigned long long r;
    asm("mov.b64 %0, {%1, %1};" : "=l"(r) : "r"(__float_as_uint(x)));
    return r;
}
DEV_INLINE void ffma2(unsigned long long& d, unsigned long long a, unsigned long long b) {
    asm("fma.rn.f32x2 %0, %1, %2, %0;" : "+l"(d) : "l"(a), "l"(b));
}
DEV_INLINE float lo2(unsigned long long v) {
    return __uint_as_float((unsigned)(v & 0xffffffffull));
}
DEV_INLINE float hi2(unsigned long long v) {
    return __uint_as_float((unsigned)(v >> 32));
}
DEV_INLINE unsigned long long pack2(float x, float y) {
    unsigned long long r;
    asm("mov.b64 %0, {%1, %2};" : "=l"(r) : "r"(__float_as_uint(x)), "r"(__float_as_uint(y)));
    return r;
}

// Split v0,v1 into bf16 hi (returned packed) and bf16 lo (out-param packed).
DEV_INLINE uint32_t pack_split(float v0, float v1, uint32_t& lo_out) {
    __nv_bfloat16 h0 = __float2bfloat16(v0);
    __nv_bfloat16 h1 = __float2bfloat16(v1);
    __nv_bfloat16 l0 = __float2bfloat16(v0 - __bfloat162float(h0));
    __nv_bfloat16 l1 = __float2bfloat16(v1 - __bfloat162float(h1));
    lo_out = ((uint32_t)__bfloat16_as_ushort(l1) << 16) | __bfloat16_as_ushort(l0);
    return ((uint32_t)__bfloat16_as_ushort(h1) << 16) | __bfloat16_as_ushort(h0);
}

// ---------------------------------------------------------------------------
// Kernel 1: fused prep + KNN (round-11 verified form: 8 keys/block, 1/warp).
// ---------------------------------------------------------------------------
__global__ void __launch_bounds__(256) knn_prep_kernel(
    const float* __restrict__ keys, const float* __restrict__ points,
    const float* __restrict__ W0, const float* __restrict__ W1)
{
    __shared__ float sp[P_ * 3];   // 48KB: points tile for knn / transpose tile for prep
    const int bx = blockIdx.x;

    if (bx < 512) {
        // --- W0 transpose-split ---
        float (*tile)[33] = (float(*)[33])sp;
        const int tx = threadIdx.x & 31, ty = threadIdx.x >> 5;
        const int k0 = (bx & 63) * 32, n0 = (bx >> 6) * 32;
#pragma unroll
        for (int i = 0; i < 4; ++i)
            tile[ty + i * 8][tx] = W0[(size_t)(k0 + ty + i * 8) * FH + n0 + tx];
        __syncthreads();
#pragma unroll
        for (int i = 0; i < 4; ++i) {
            const int nn = n0 + ty + i * 8, kk = k0 + tx;
            const float v = tile[tx][ty + i * 8];
            __nv_bfloat16 h = __float2bfloat16(v);
            g_Whi[(size_t)nn * EDIM + kk] = h;
            g_Wlo[(size_t)nn * EDIM + kk] = __float2bfloat16(v - __bfloat162float(h));
        }
        return;
    }
    if (bx < 640) {
        // --- W1 split ---
        const int idx = (bx - 512) * 256 + threadIdx.x;   // 0..32767
        const int nn = idx >> 8, kk = idx & 255;
        const float v = W1[kk * COUT + nn];
        __nv_bfloat16 h = __float2bfloat16(v);
        g_W1hi[nn * FH + kk] = h;
        g_W1lo[nn * FH + kk] = __float2bfloat16(v - __bfloat162float(h));
        return;
    }

    // --- KNN: 8 keys per block, 1 key per warp ---
    const int kb = bx - 640;
    const int warp = threadIdx.x >> 5;
    const int lane = threadIdx.x & 31;
    const int g = kb * 8 + warp;
    const int b = g >> 11;
    const unsigned FULL = 0xffffffffu;

    const float* pb = points + (size_t)b * P_ * 3;
    for (int i = threadIdx.x; i < P_ * 3; i += 256) sp[i] = pb[i];
    __syncthreads();

    const float kx = keys[g * 3 + 0];
    const float ky = keys[g * 3 + 1];
    const float kz = keys[g * 3 + 2];

    float ld = 3.4e38f;          // distributed list entry (lanes 0..15 valid)
    int   li = 0x7fffffff;
    float warpMax = 3.4e38f;     // current 16th smallest (uniform)

    for (int p = lane; p < P_; p += 32) {
        float dx = __fsub_rn(sp[p * 3 + 0], kx);
        float dy = __fsub_rn(sp[p * 3 + 1], ky);
        float dz = __fsub_rn(sp[p * 3 + 2], kz);
        float d  = __fadd_rn(__fadd_rn(__fmul_rn(dx, dx), __fmul_rn(dy, dy)),
                             __fmul_rn(dz, dz));

        unsigned hit = __ballot_sync(FULL, d < warpMax);
        while (hit) {
            const int src = __ffs(hit) - 1;
            hit &= hit - 1;
            const float dc = __shfl_sync(FULL, d, src);
            const int   ic = __shfl_sync(FULL, p, src);
            if (dc < warpMax) {   // recheck: warpMax tightens within this loop
                const unsigned bal =
                    __ballot_sync(FULL, (lane < NB) && (ld <= dc));
                const int pos = __popc(bal);
                const float pd = __shfl_up_sync(FULL, ld, 1);
                const int   pi = __shfl_up_sync(FULL, li, 1);
                if (lane >= pos && lane < NB) {
                    ld = (lane == pos) ? dc : pd;
                    li = (lane == pos) ? ic : pi;
                }
                warpMax = __shfl_sync(FULL, ld, NB - 1);
            }
        }
    }
    if (lane < NB) g_idx[g * NB + lane] = li;
}

// ---------------------------------------------------------------------------
// Kernel 2: per-edge weight MLP + aggregation -> E (bf16 hi/lo).
// NEW: FFMA2 (fp32x2) throughout the hot loops:
//  - layers 2/3 use natural [in][out] weight layout so output-pairs are
//    adjacent 64-bit words; accumulators are packed pairs.
//  - aggregation accumulates {e0[2j],e0[2j+1]} pairs against adjacent m pairs.
// Same fp32 math per accumulator (order preserved) -> no accuracy change.
// ---------------------------------------------------------------------------
__global__ void __launch_bounds__(128) edge_kernel(
    const float* __restrict__ keys, const float* __restrict__ points,
    const float* __restrict__ feats,
    const float* __restrict__ w0, const float* __restrict__ b0,
    const float* __restrict__ w1, const float* __restrict__ b1,
    const float* __restrict__ w2, const float* __restrict__ b2)
{
    __shared__ __align__(16) float sw0[3][32];
    __shared__ __align__(8)  float sb0[32], sb1[32], sb2[32];
    __shared__ __align__(16) float sw1[32][32];   // [in][out] natural layout
    __shared__ __align__(16) float sw2[32][32];
    __shared__ __align__(16) float sm_m[4][NB][32];
    __shared__ __align__(16) float sm_f[4][NB][CIN];

    const int t = threadIdx.x;
    const int w = t >> 5, lane = t & 31;

    for (int i = t; i < 96; i += 128) sw0[i / 32][i % 32] = w0[i];
    if (t < 32) { sb0[t] = b0[t]; sb1[t] = b1[t]; sb2[t] = b2[t]; }
    for (int i = t; i < 1024; i += 128) {
        ((float*)sw1)[i] = w1[i];   // natural [in][out]
        ((float*)sw2)[i] = w2[i];
    }
    __syncthreads();

    const int g = blockIdx.x * 4 + w;
    const int b = g >> 11;

    const int n  = lane >> 1;          // neighbor handled by this lane pair
    const int jb = (lane & 1) * 16;    // output half

    const int gi = g_idx[g * NB + n];

    // Full-warp feature gather: 256 float4 total, 8 per lane.
#pragma unroll
    for (int i = 0; i < 8; ++i) {
        const int ii = lane + i * 32;
        const int nn = ii >> 4, q = ii & 15;
        const int gin = __shfl_sync(0xffffffffu, gi, nn * 2);
        *(float4*)&sm_f[w][nn][q * 4] =
            *(const float4*)&feats[((size_t)b * P_ + gin) * CIN + q * 4];
    }

    // Layer 1 (3 -> 32): scalar, 48 fma per lane.
    const float rx = points[((size_t)b * P_ + gi) * 3 + 0] - keys[g * 3 + 0];
    const float ry = points[((size_t)b * P_ + gi) * 3 + 1] - keys[g * 3 + 1];
    const float rz = points[((size_t)b * P_ + gi) * 3 + 2] - keys[g * 3 + 2];

    float h1[16];
#pragma unroll
    for (int j = 0; j < 16; ++j) {
        const int jj = jb + j;
        h1[j] = fmaxf(fmaf(rx, sw0[0][jj], fmaf(ry, sw0[1][jj],
                      fmaf(rz, sw0[2][jj], sb0[jj]))), 0.0f);
    }
    float h1o[16];
#pragma unroll
    for (int j = 0; j < 16; ++j) h1o[j] = __shfl_xor_sync(0xffffffffu, h1[j], 1);

    // Layer 2 (32 -> 32), FFMA2 over output pairs.
    unsigned long long A2[8];
    {
        const unsigned long long* bp = (const unsigned long long*)sb1 + (jb >> 1);
#pragma unroll
        for (int q = 0; q < 8; ++q) A2[q] = bp[q];
#pragma unroll
        for (int i = 0; i < 16; ++i) {
            const unsigned long long a0 = splat2(h1[i]);
            const unsigned long long* br =
                (const unsigned long long*)(&sw1[jb + i][jb]);
#pragma unroll
            for (int q = 0; q < 8; ++q) ffma2(A2[q], a0, br[q]);
            const unsigned long long a1 = splat2(h1o[i]);
            const unsigned long long* bo =
                (const unsigned long long*)(&sw1[(jb ^ 16) + i][jb]);
#pragma unroll
            for (int q = 0; q < 8; ++q) ffma2(A2[q], a1, bo[q]);
        }
    }
    float h2[16];
#pragma unroll
    for (int q = 0; q < 8; ++q) {
        h2[2 * q]     = fmaxf(lo2(A2[q]), 0.0f);
        h2[2 * q + 1] = fmaxf(hi2(A2[q]), 0.0f);
    }
    float h2o[16];
#pragma unroll
    for (int j = 0; j < 16; ++j) h2o[j] = __shfl_xor_sync(0xffffffffu, h2[j], 1);

    // Layer 3 (32 -> 32, linear), FFMA2 over output pairs -> sm_m.
    {
        unsigned long long A3[8];
        const unsigned long long* bp = (const unsigned long long*)sb2 + (jb >> 1);
#pragma unroll
        for (int q = 0; q < 8; ++q) A3[q] = bp[q];
#pragma unroll
        for (int i = 0; i < 16; ++i) {
            const unsigned long long a0 = splat2(h2[i]);
            const unsigned long long* br =
                (const unsigned long long*)(&sw2[jb + i][jb]);
#pragma unroll
            for (int q = 0; q < 8; ++q) ffma2(A3[q], a0, br[q]);
            const unsigned long long a1 = splat2(h2o[i]);
            const unsigned long long* bo =
                (const unsigned long long*)(&sw2[(jb ^ 16) + i][jb]);
#pragma unroll
            for (int q = 0; q < 8; ++q) ffma2(A3[q], a1, bo[q]);
        }
        unsigned long long* mdst =
            (unsigned long long*)sm_m[w][n] + (jb >> 1);
#pragma unroll
        for (int q = 0; q < 8; ++q) mdst[q] = A3[q];
    }
    __syncwarp();

    // Aggregation with FFMA2: E0[j] = {e0[2j], e0[2j+1]}, e0[mc] = sum_n m[n][mc]*f.x
    unsigned long long E0[16], E1[16];
#pragma unroll
    for (int j = 0; j < 16; ++j) { E0[j] = 0ull; E1[j] = 0ull; }

#pragma unroll
    for (int nn = 0; nn < NB; ++nn) {
        const float2 f = *(const float2*)&sm_f[w][nn][2 * lane];
        const unsigned long long ax = splat2(f.x);
        const unsigned long long ay = splat2(f.y);
        const ulonglong2* mp = (const ulonglong2*)sm_m[w][nn];
#pragma unroll
        for (int qq = 0; qq < 8; ++qq) {
            const ulonglong2 mv = mp[qq];
            ffma2(E0[2 * qq],     ax, mv.x);
            ffma2(E0[2 * qq + 1], ax, mv.y);
            ffma2(E1[2 * qq],     ay, mv.x);
            ffma2(E1[2 * qq + 1], ay, mv.y);
        }
    }

    uint32_t* EhP = (uint32_t*)(g_Ehi + (size_t)g * EDIM);
    uint32_t* ElP = (uint32_t*)(g_Elo + (size_t)g * EDIM);
#pragma unroll
    for (int j = 0; j < 16; ++j) {
        uint32_t lo;
        uint32_t hi = pack_split(lo2(E0[j]), lo2(E1[j]), lo);   // mc = 2j
        EhP[(2 * j) * 32 + lane] = hi;
        ElP[(2 * j) * 32 + lane] = lo;
        hi = pack_split(hi2(E0[j]), hi2(E1[j]), lo);            // mc = 2j+1
        EhP[(2 * j + 1) * 32 + lane] = hi;
        ElP[(2 * j + 1) * 32 + lane] = lo;
    }
}

// ---------------------------------------------------------------------------
// Kernel 3: gemm1 HMMA — H = relu(E @ W0 + b0), 3-term bf16 split, 128x128,
// BK=64, 3-stage cp.async pipeline, single-buffered fragments. (unchanged)
// ---------------------------------------------------------------------------
constexpr int G1_STAGE  = 4 * 16384;          // Ahi, Alo, Bhi, Blo (64KB)
constexpr int G1_STAGES = 3;
constexpr int G1_SMEM   = G1_STAGES * G1_STAGE;   // 196608
constexpr int G1_NI     = EDIM / 64;          // 32

__global__ void __launch_bounds__(256, 1) gemm1_mma_kernel(const float* __restrict__ bias)
{
    extern __shared__ char smem[];
    const uint32_t base = smem_u32(smem);
    const int tid  = threadIdx.x;
    const int wid  = tid >> 5;
    const int lane = tid & 31;
    const int m0 = blockIdx.y * 128;
    const int n0 = blockIdx.x * 128;
    const int warpM = (wid & 1) * 64;
    const int warpN = (wid >> 1) * 32;

    const __nv_bfloat16* srcA_hi = g_Ehi + (size_t)m0 * EDIM;
    const __nv_bfloat16* srcA_lo = g_Elo + (size_t)m0 * EDIM;
    const __nv_bfloat16* srcB_hi = g_Whi + (size_t)n0 * EDIM;
    const __nv_bfloat16* srcB_lo = g_Wlo + (size_t)n0 * EDIM;

    auto load_stage = [&](int it, int slot) {
        const uint32_t sb = base + slot * G1_STAGE;
        const int k0 = it * 64;
        const __nv_bfloat16* srcs[4] = {srcA_hi, srcA_lo, srcB_hi, srcB_lo};
#pragma unroll
        for (int sub = 0; sub < 4; ++sub) {
            const __nv_bfloat16* sp = srcs[sub] + k0;
            const uint32_t sbase = sb + sub * 16384;
#pragma unroll
            for (int j = 0; j < 4; ++j) {
                const int idx = tid + j * 256;
                const int r = idx >> 3, c = idx & 7;
                const uint32_t off = (uint32_t)idx * 16;
                const uint32_t dst = sbase + (off ^ ((off >> 3) & 0x70));
                cp_async16(dst, sp + (size_t)r * EDIM + c * 8);
            }
        }
    };

    float acc[4][4][4];
#pragma unroll
    for (int i = 0; i < 4; ++i)
#pragma unroll
        for (int j = 0; j < 4; ++j)
#pragma unroll
            for (int q = 0; q < 4; ++q) acc[i][j][q] = 0.0f;

    const int aRow = ((lane >> 3) & 1) * 8 + (lane & 7);
    const int aKof = (lane >> 4) * 8;
    const int bRow = ((lane >> 4) & 1) * 8 + (lane & 7);
    const int bKof = ((lane >> 3) & 1) * 8;

    load_stage(0, 0);
    cp_commit();
    load_stage(1, 1);
    cp_commit();

    int cslot = 0;   // slot holding stage `it`
    int lslot = 2;   // slot to load stage `it+2` into

    for (int it = 0; it < G1_NI; ++it) {
        if (it == G1_NI - 1) cp_wait<0>(); else cp_wait<1>();
        __syncthreads();   // all warps past compute(it-1); slot lslot reusable

        if (it + 2 < G1_NI) {
            load_stage(it + 2, lslot);
            cp_commit();
            if (++lslot == G1_STAGES) lslot = 0;
        }

        const uint32_t sb = base + cslot * G1_STAGE;
        if (++cslot == G1_STAGES) cslot = 0;
        const uint32_t sA_hi = sb;
        const uint32_t sA_lo = sb + 16384;
        const uint32_t sB_hi = sb + 32768;
        const uint32_t sB_lo = sb + 49152;

#pragma unroll
        for (int kk = 0; kk < 4; ++kk) {
            const int k0 = kk * 16;
            uint32_t ah[4][4], al[4][4], bh[2][4], bl[2][4];
#pragma unroll
            for (int mi = 0; mi < 4; ++mi) {
                const int row = warpM + mi * 16 + aRow;
                const int col = k0 + aKof;
                const uint32_t off = (uint32_t)(row * 128 + col * 2);
                const uint32_t sw  = off ^ ((off >> 3) & 0x70);
                ldm_x4(ah[mi], sA_hi + sw);
                ldm_x4(al[mi], sA_lo + sw);
            }
#pragma unroll
            for (int nj = 0; nj < 2; ++nj) {
                const int row = warpN + nj * 16 + bRow;
                const int col = k0 + bKof;
                const uint32_t off = (uint32_t)(row * 128 + col * 2);
                const uint32_t sw  = off ^ ((off >> 3) & 0x70);
                ldm_x4(bh[nj], sB_hi + sw);
                ldm_x4(bl[nj], sB_lo + sw);
            }
#pragma unroll
            for (int mi = 0; mi < 4; ++mi)
#pragma unroll
                for (int nj = 0; nj < 2; ++nj)
#pragma unroll
                    for (int nk = 0; nk < 2; ++nk) {
                        float* d = acc[mi][nj * 2 + nk];
                        mma_bf16(d, ah[mi], bh[nj][nk * 2], bh[nj][nk * 2 + 1]);
                        mma_bf16(d, ah[mi], bl[nj][nk * 2], bl[nj][nk * 2 + 1]);
                        mma_bf16(d, al[mi], bh[nj][nk * 2], bh[nj][nk * 2 + 1]);
                    }
        }
    }

    // Epilogue: bias + relu, split to bf16 hi/lo, packed u32 stores.
#pragma unroll
    for (int mi = 0; mi < 4; ++mi) {
        const int row = m0 + warpM + mi * 16 + (lane >> 2);
#pragma unroll
        for (int ni = 0; ni < 4; ++ni) {
            const int col = n0 + warpN + ni * 8 + 2 * (lane & 3);
            const float b0v = bias[col], b1v = bias[col + 1];
            const float v0 = fmaxf(acc[mi][ni][0] + b0v, 0.0f);
            const float v1 = fmaxf(acc[mi][ni][1] + b1v, 0.0f);
            const float v2 = fmaxf(acc[mi][ni][2] + b0v, 0.0f);
            const float v3 = fmaxf(acc[mi][ni][3] + b1v, 0.0f);
            uint32_t lo01, lo23;
            const uint32_t hi01 = pack_split(v0, v1, lo01);
            const uint32_t hi23 = pack_split(v2, v3, lo23);
            ((uint32_t*)(g_Hhi + (size_t)row * FH))[col >> 1]       = hi01;
            ((uint32_t*)(g_Hlo + (size_t)row * FH))[col >> 1]       = lo01;
            ((uint32_t*)(g_Hhi + (size_t)(row + 8) * FH))[col >> 1] = hi23;
            ((uint32_t*)(g_Hlo + (size_t)(row + 8) * FH))[col >> 1] = lo23;
        }
    }
}

// ---------------------------------------------------------------------------
// Kernel 4: gemm2 HMMA — out = H @ W1 + b1, 3-term bf16 split.
// FULL PREFETCH (measured win). (unchanged)
// ---------------------------------------------------------------------------
constexpr int G2_A_BYTES = 64 * 64 * 2;        // 8192
constexpr int G2_B_BYTES = 128 * 64 * 2;       // 16384
constexpr int G2_STAGE   = 2 * G2_A_BYTES + 2 * G2_B_BYTES;   // 49152
constexpr int G2_NI      = FH / 64;            // 4
constexpr int G2_SMEM    = G2_NI * G2_STAGE;   // 196608

__global__ void __launch_bounds__(256, 1) gemm2_mma_kernel(const float* __restrict__ bias,
                                                           float* __restrict__ C)
{
    extern __shared__ char smem[];
    const uint32_t base = smem_u32(smem);
    const int tid  = threadIdx.x;
    const int wid  = tid >> 5;
    const int lane = tid & 31;
    const int m0 = blockIdx.y * 64;
    const int warpM = (wid & 1) * 32;
    const int warpN = (wid >> 1) * 32;

    const __nv_bfloat16* srcA_hi = g_Hhi + (size_t)m0 * FH;
    const __nv_bfloat16* srcA_lo = g_Hlo + (size_t)m0 * FH;

    auto load_stage = [&](int it) {
        const uint32_t sb = base + it * G2_STAGE;
        const int k0 = it * 64;
#pragma unroll
        for (int s = 0; s < 2; ++s) {
            const __nv_bfloat16* sp = (s == 0 ? srcA_hi : srcA_lo) + k0;
            const uint32_t sbase = sb + s * G2_A_BYTES;
#pragma unroll
            for (int j = 0; j < 2; ++j) {
                const int idx = tid + j * 256;              // 0..511
                const int r = idx >> 3, c = idx & 7;
                const uint32_t off = (uint32_t)idx * 16;
                const uint32_t dst = sbase + (off ^ ((off >> 3) & 0x70));
                cp_async16(dst, sp + (size_t)r * FH + c * 8);
            }
        }
#pragma unroll
        for (int s = 0; s < 2; ++s) {
            const __nv_bfloat16* sp = (s == 0 ? g_W1hi : g_W1lo) + k0;
            const uint32_t sbase = sb + 2 * G2_A_BYTES + s * G2_B_BYTES;
#pragma unroll
            for (int j = 0; j < 4; ++j) {
                const int idx = tid + j * 256;              // 0..1023
                const int r = idx >> 3, c = idx & 7;
                const uint32_t off = (uint32_t)idx * 16;
                const uint32_t dst = sbase + (off ^ ((off >> 3) & 0x70));
                cp_async16(dst, sp + (size_t)r * FH + c * 8);
            }
        }
    };

    float acc[2][4][4];
#pragma unroll
    for (int i = 0; i < 2; ++i)
#pragma unroll
        for (int j = 0; j < 4; ++j)
#pragma unroll
            for (int q = 0; q < 4; ++q) acc[i][j][q] = 0.0f;

    const int aRow = ((lane >> 3) & 1) * 8 + (lane & 7);
    const int aKof = (lane >> 4) * 8;
    const int bRow = ((lane >> 4) & 1) * 8 + (lane & 7);
    const int bKof = ((lane >> 3) & 1) * 8;

    // Issue ALL stages up front.
#pragma unroll
    for (int it = 0; it < G2_NI; ++it) {
        load_stage(it);
        cp_commit();
    }

#pragma unroll
    for (int it = 0; it < G2_NI; ++it) {
        switch (G2_NI - 1 - it) {   // groups still allowed in flight
            case 3: cp_wait<3>(); break;
            case 2: cp_wait<2>(); break;
            case 1: cp_wait<1>(); break;
            default: cp_wait<0>(); break;
        }
        __syncthreads();

        const uint32_t sb = base + it * G2_STAGE;
        const uint32_t sA_hi = sb;
        const uint32_t sA_lo = sb + G2_A_BYTES;
        const uint32_t sB_hi = sb + 2 * G2_A_BYTES;
        const uint32_t sB_lo = sb + 2 * G2_A_BYTES + G2_B_BYTES;

#pragma unroll
        for (int kk = 0; kk < 4; ++kk) {
            const int k0 = kk * 16;
            uint32_t ah[2][4], al[2][4], bh[2][4], bl[2][4];
#pragma unroll
            for (int mi = 0; mi < 2; ++mi) {
                const int row = warpM + mi * 16 + aRow;
                const int col = k0 + aKof;
                const uint32_t off = (uint32_t)(row * 128 + col * 2);
                const uint32_t sw  = off ^ ((off >> 3) & 0x70);
                ldm_x4(ah[mi], sA_hi + sw);
                ldm_x4(al[mi], sA_lo + sw);
            }
#pragma unroll
            for (int nj = 0; nj < 2; ++nj) {
                const int row = warpN + nj * 16 + bRow;
                const int col = k0 + bKof;
                const uint32_t off = (uint32_t)(row * 128 + col * 2);
                const uint32_t sw  = off ^ ((off >> 3) & 0x70);
                ldm_x4(bh[nj], sB_hi + sw);
                ldm_x4(bl[nj], sB_lo + sw);
            }
#pragma unroll
            for (int mi = 0; mi < 2; ++mi)
#pragma unroll
                for (int nj = 0; nj < 2; ++nj)
#pragma unroll
                    for (int nk = 0; nk < 2; ++nk) {
                        float* d = acc[mi][nj * 2 + nk];
                        mma_bf16(d, ah[mi], bh[nj][nk * 2], bh[nj][nk * 2 + 1]);
                        mma_bf16(d, ah[mi], bl[nj][nk * 2], bl[nj][nk * 2 + 1]);
                        mma_bf16(d, al[mi], bh[nj][nk * 2], bh[nj][nk * 2 + 1]);
                    }
        }
    }

    // Epilogue: bias, fp32 out (no relu)
#pragma unroll
    for (int mi = 0; mi < 2; ++mi) {
        const int row = m0 + warpM + mi * 16 + (lane >> 2);
#pragma unroll
        for (int ni = 0; ni < 4; ++ni) {
            const int col = warpN + ni * 8 + 2 * (lane & 3);
            const float b0v = bias[col], b1v = bias[col + 1];
            float2 v0, v1;
            v0.x = acc[mi][ni][0] + b0v;
            v0.y = acc[mi][ni][1] + b1v;
            v1.x = acc[mi][ni][2] + b0v;
            v1.y = acc[mi][ni][3] + b1v;
            *(float2*)&C[(size_t)row * COUT + col]       = v0;
            *(float2*)&C[(size_t)(row + 8) * COUT + col] = v1;
        }
    }
}

// ---------------------------------------------------------------------------
extern "C" void kernel_launch(void* const* d_in, const int* in_sizes, int n_in,
                              void* d_out, int out_size)
{
    const float* keys   = (const float*)d_in[0];
    const float* points = (const float*)d_in[1];
    const float* feats  = (const float*)d_in[2];
    const float* wc0W   = (const float*)d_in[3];
    const float* wc0b   = (const float*)d_in[4];
    const float* wc1W   = (const float*)d_in[5];
    const float* wc1b   = (const float*)d_in[6];
    const float* wc2W   = (const float*)d_in[7];
    const float* wc2b   = (const float*)d_in[8];
    const float* fc0W   = (const float*)d_in[9];
    const float* fc0b   = (const float*)d_in[10];
    const float* fc1W   = (const float*)d_in[11];
    const float* fc1b   = (const float*)d_in[12];
    float* out = (float*)d_out;

    cudaFuncSetAttribute(gemm1_mma_kernel,
                         cudaFuncAttributeMaxDynamicSharedMemorySize, G1_SMEM);
    cudaFuncSetAttribute(gemm2_mma_kernel,
                         cudaFuncAttributeMaxDynamicSharedMemorySize, G2_SMEM);

    knn_prep_kernel<<<640 + GK / 8, 256>>>(keys, points, fc0W, fc1W);
    edge_kernel<<<GK / 4, 128>>>(keys, points, feats,
                                 wc0W, wc0b, wc1W, wc1b, wc2W, wc2b);
    gemm1_mma_kernel<<<dim3(FH / 128, GK / 128), 256, G1_SMEM>>>(fc0b);
    gemm2_mma_kernel<<<dim3(1, GK / 64), 256, G2_SMEM>>>(fc1b, out);
}